// round 1
// baseline (speedup 1.0000x reference)
#include <cuda_runtime.h>
#include <math.h>

#define BB 16
#define NN 2048
#define MM 32
#define PP 48
#define TT 5
#define CC (PP*TT)   // 240

#define APB 4        // atoms per block (kernel 1)
#define TH1 256

// ---------------------------------------------------------------------------
// Kernel 1: radial symmetry functions, bucketed by atom type.
// Phase A: warp w (< APB) handles atom (blockIdx*APB + w); lane = neighbor m.
//          Computes R, maps Z -> type bin, compacts R into per-type buckets
//          in shared memory via warp ballot (invalid types dropped entirely).
// Phase B: 64-thread group g handles atom g; thread j < 48 is radial index p.
//          For each type bucket, accumulate exp(-re (R-rs)^2)*cutoff, write
//          layer[b,n, t*48+p] directly into d_out.
// ---------------------------------------------------------------------------
__global__ __launch_bounds__(TH1)
void rsf_kernel(const float* __restrict__ X,
                const float* __restrict__ rc,
                const float* __restrict__ rs,
                const float* __restrict__ re,
                const int*   __restrict__ Nbrs,
                const int*   __restrict__ NbrsZ,
                float*       __restrict__ out)
{
    __shared__ float sR[APB][MM];
    __shared__ int   sOff[APB][TT + 1];

    const int tid  = threadIdx.x;
    const int warp = tid >> 5;
    const int lane = tid & 31;
    const int baseAtom = blockIdx.x * APB;      // atom = b*N + n

    // ---------------- Phase A ----------------
    if (warp < APB) {
        const int atom = baseAtom + warp;
        const int b    = atom >> 11;            // atom / N
        const float* xp = X + atom * 3;
        const float x0 = xp[0], x1 = xp[1], x2 = xp[2];

        const int nb = Nbrs [atom * MM + lane];
        const int z  = NbrsZ[atom * MM + lane];
        const float* np_ = X + ((b << 11) + nb) * 3;
        const float dx = np_[0] - x0;
        const float dy = np_[1] - x1;
        const float dz = np_[2] - x2;
        const float R  = sqrtf(dx*dx + dy*dy + dz*dz);

        int t = -1;
        if      (z == 1)  t = 0;
        else if (z == 6)  t = 1;
        else if (z == 7)  t = 2;
        else if (z == 8)  t = 3;
        else if (z == 16) t = 4;

        int base = 0;
        const unsigned lt = (1u << lane) - 1u;
        #pragma unroll
        for (int tt = 0; tt < TT; tt++) {
            unsigned mask = __ballot_sync(0xffffffffu, t == tt);
            if (t == tt) {
                sR[warp][base + __popc(mask & lt)] = R;
            }
            if (lane == 0) sOff[warp][tt] = base;
            base += __popc(mask);
        }
        if (lane == 0) sOff[warp][TT] = base;
    }
    __syncthreads();

    // ---------------- Phase B ----------------
    const int g = tid >> 6;        // atom within block
    const int j = tid & 63;        // p index
    if (j < PP) {
        const int atom = baseAtom + g;
        const float myrc  = rc[j];
        const float myrs  = rs[j];
        const float nre   = -re[j];
        const float pi_rc = 3.14159265358979f / myrc;
        float* op = out + (size_t)atom * CC;

        #pragma unroll
        for (int tt = 0; tt < TT; tt++) {
            const int mb = sOff[g][tt];
            const int me = sOff[g][tt + 1];
            float acc = 0.0f;
            for (int m = mb; m < me; m++) {
                const float R  = sR[g][m];
                const float dr = R - myrs;
                const float ex = __expf(nre * dr * dr);
                const float fc = 0.5f * __cosf(R * pi_rc) + 0.5f;
                const float v  = ex * fc;
                acc += (R <= myrc) ? v : 0.0f;
            }
            op[tt * PP + j] = acc;
        }
    }
}

// ---------------------------------------------------------------------------
// Kernel 2: BatchNorm1d(num_features=N), training mode, affine identity.
// One block per n: reduce mean/var over the 3840 values layer[:, n, :],
// stage values in smem, normalize in place.
// ---------------------------------------------------------------------------
__global__ __launch_bounds__(256)
void bn_kernel(float* __restrict__ out)
{
    const int n   = blockIdx.x;
    const int tid = threadIdx.x;

    __shared__ float vals[BB * CC];        // 3840 floats = 15 KB
    __shared__ float wsum[8], wsum2[8];

    float s = 0.0f, s2 = 0.0f;
    #pragma unroll
    for (int b = 0; b < BB; b++) {
        if (tid < CC) {
            const float v = out[((size_t)(b * NN + n)) * CC + tid];
            vals[b * CC + tid] = v;
            s  += v;
            s2 += v * v;
        }
    }

    // block reduction (8 warps)
    #pragma unroll
    for (int o = 16; o > 0; o >>= 1) {
        s  += __shfl_down_sync(0xffffffffu, s,  o);
        s2 += __shfl_down_sync(0xffffffffu, s2, o);
    }
    const int warp = tid >> 5, lane = tid & 31;
    if (lane == 0) { wsum[warp] = s; wsum2[warp] = s2; }
    __syncthreads();
    if (warp == 0) {
        float a  = (lane < 8) ? wsum[lane]  : 0.0f;
        float a2 = (lane < 8) ? wsum2[lane] : 0.0f;
        #pragma unroll
        for (int o = 4; o > 0; o >>= 1) {
            a  += __shfl_down_sync(0xffffffffu, a,  o);
            a2 += __shfl_down_sync(0xffffffffu, a2, o);
        }
        if (lane == 0) { wsum[0] = a; wsum2[0] = a2; }
    }
    __syncthreads();

    const float invn = 1.0f / (float)(BB * CC);
    const float mean = wsum[0] * invn;
    float var = wsum2[0] * invn - mean * mean;
    var = fmaxf(var, 0.0f);
    const float inv = rsqrtf(var + 1e-5f);

    #pragma unroll
    for (int b = 0; b < BB; b++) {
        if (tid < CC) {
            out[((size_t)(b * NN + n)) * CC + tid] =
                (vals[b * CC + tid] - mean) * inv;
        }
    }
}

// ---------------------------------------------------------------------------
extern "C" void kernel_launch(void* const* d_in, const int* in_sizes, int n_in,
                              void* d_out, int out_size)
{
    const float* X     = (const float*)d_in[0];
    const float* rc    = (const float*)d_in[1];
    const float* rs    = (const float*)d_in[2];
    const float* re    = (const float*)d_in[3];
    const int*   Nbrs  = (const int*)  d_in[4];
    const int*   NbrsZ = (const int*)  d_in[5];
    float* out = (float*)d_out;

    const int nAtoms = BB * NN;                 // 32768
    rsf_kernel<<<nAtoms / APB, TH1>>>(X, rc, rs, re, Nbrs, NbrsZ, out);
    bn_kernel<<<NN, 256>>>(out);
}